// round 3
// baseline (speedup 1.0000x reference)
#include <cuda_runtime.h>
#include <cuda_bf16.h>
#include <math.h>

// ---------------------------------------------------------------------------
// Problem constants
// ---------------------------------------------------------------------------
#define BATCH 4
#define LIN   40960
#define CCH   512
#define T0    8192
#define T1    2048
#define T2    1024
#define T3    512
#define TN    256
#define DMLP  2048

// ---------------------------------------------------------------------------
// Scratch (device globals; no allocation allowed)
// ---------------------------------------------------------------------------
__device__ float g_h0[BATCH * T0 * CCH];      // 64 MB  [b][t][c]
__device__ float g_h1[BATCH * T1 * CCH];      // 16 MB
__device__ float g_h2[BATCH * T2 * CCH];      //  8 MB
__device__ float g_f [BATCH * T3 * CCH];      //  4 MB  (features for MLP + pooling)
__device__ float g_z1[BATCH * T3 * DMLP];     // 16 MB
__device__ float g_z2[BATCH * T3 * DMLP];     // 16 MB
__device__ float g_imp[BATCH * T3];
__device__ float g_cs [BATCH * T3];
__device__ float g_w0t[10 * CCH];
__device__ float g_w1t[CCH * 8 * CCH];        //  8 MB
__device__ float g_w2t[CCH * 4 * CCH];        //  4 MB
__device__ float g_w3t[CCH * 4 * CCH];        //  4 MB

// ---------------------------------------------------------------------------
// Helpers
// ---------------------------------------------------------------------------
__device__ __forceinline__ int refl(int p, int n) {
    return p < 0 ? -p : (p >= n ? 2 * n - 2 - p : p);
}

__device__ __forceinline__ float gelu_exact(float v) {
    return 0.5f * v * (1.f + erff(v * 0.70710678118654752f));
}

// Block-wide (sum, sumsq) reduction. sred must hold >= 64 floats.
__device__ __forceinline__ float2 block_reduce2(float v1, float v2, float* sred) {
    __syncthreads();  // protect sred reuse across calls
    int lane = threadIdx.x & 31, wid = threadIdx.x >> 5;
    int nw = blockDim.x >> 5;
#pragma unroll
    for (int o = 16; o > 0; o >>= 1) {
        v1 += __shfl_down_sync(0xffffffffu, v1, o);
        v2 += __shfl_down_sync(0xffffffffu, v2, o);
    }
    if (lane == 0) { sred[wid] = v1; sred[wid + 32] = v2; }
    __syncthreads();
    if (wid == 0) {
        v1 = (lane < nw) ? sred[lane] : 0.f;
        v2 = (lane < nw) ? sred[lane + 32] : 0.f;
#pragma unroll
        for (int o = 16; o > 0; o >>= 1) {
            v1 += __shfl_down_sync(0xffffffffu, v1, o);
            v2 += __shfl_down_sync(0xffffffffu, v2, o);
        }
        if (lane == 0) { sred[0] = v1; sred[32] = v2; }
    }
    __syncthreads();
    return make_float2(sred[0], sred[32]);
}

// ---------------------------------------------------------------------------
// Weight transpose: w[c][ci][k] -> wt[(ci*KW+k)*512 + c]
// ---------------------------------------------------------------------------
__global__ void k_wtrans(const float* __restrict__ w, float* __restrict__ wt,
                         int CI, int KW, int total) {
    int idx = blockIdx.x * blockDim.x + threadIdx.x;
    if (idx < total) {
        int ck = CI * KW;
        int c = idx / ck;
        int r = idx - c * ck;
        wt[r * CCH + c] = w[idx];
    }
}

// ---------------------------------------------------------------------------
// conv0 (1->512, k=10, s=5, reflect pad 3) + ChannelNorm + ReLU
// grid (T0/8, B), block 512 (one thread per channel)
// ---------------------------------------------------------------------------
__global__ __launch_bounds__(512) void k_conv0(
    const float* __restrict__ x, const float* __restrict__ w0t,
    const float* __restrict__ bias, const float* __restrict__ nw,
    const float* __restrict__ nb, float* __restrict__ out) {
    const int TT = 8, KW = 10, S = 5, PAD = 3;
    const int W = S * (TT - 1) + KW;  // 45
    __shared__ float sx[48];
    __shared__ float sred[64];
    int b = blockIdx.y, t0 = blockIdx.x * TT, c = threadIdx.x;
    if (c < W) {
        int p = refl(S * t0 - PAD + c, LIN);
        sx[c] = x[b * LIN + p];
    }
    __syncthreads();
    float acc[TT];
    float bi = bias[c];
#pragma unroll
    for (int tt = 0; tt < TT; tt++) acc[tt] = bi;
#pragma unroll
    for (int k = 0; k < KW; k++) {
        float w = w0t[k * CCH + c];
#pragma unroll
        for (int tt = 0; tt < TT; tt++) acc[tt] = fmaf(w, sx[S * tt + k], acc[tt]);
    }
    float gw = nw[c], gb = nb[c];
    for (int tt = 0; tt < TT; tt++) {
        float2 s = block_reduce2(acc[tt], acc[tt] * acc[tt], sred);
        float mean = s.x * (1.f / 512.f);
        float var  = (s.y - s.x * s.x * (1.f / 512.f)) * (1.f / 511.f);
        float inv  = rsqrtf(var + 1e-5f);
        float v    = (acc[tt] - mean) * inv * gw + gb;
        out[((size_t)(b * T0 + t0 + tt)) * CCH + c] = fmaxf(v, 0.f);
    }
}

// ---------------------------------------------------------------------------
// Fused conv (512->512) + ChannelNorm + ReLU, high FMA density.
// block 128 threads; thread j handles 4 channels c = 4j..4j+3 (LDG.128 weights),
// TT time-steps. Inner pattern per smem value: 1 broadcast LDS + 4 FFMA.
// Input/output layout [b][t][c].
// ---------------------------------------------------------------------------
template <int KW, int S, int PAD, int TT>
__global__ __launch_bounds__(128, 3) void k_conv(
    const float* __restrict__ xin, int TINv, int TOUTv,
    const float* __restrict__ wt, const float* __restrict__ bias,
    const float* __restrict__ nw, const float* __restrict__ nb,
    float* __restrict__ out) {
    constexpr int W = S * (TT - 1) + KW;
    __shared__ float sx[W * 128];
    __shared__ float sred[64];
    int b = blockIdx.y, t0 = blockIdx.x * TT, j = threadIdx.x;
    int c0 = j * 4;
    float acc[4][TT];
    float4 bi = *(const float4*)(bias + c0);
#pragma unroll
    for (int tt = 0; tt < TT; tt++) {
        acc[0][tt] = bi.x; acc[1][tt] = bi.y; acc[2][tt] = bi.z; acc[3][tt] = bi.w;
    }
    int base = S * t0 - PAD;
    for (int cc = 0; cc < CCH; cc += 128) {
        __syncthreads();
        // stage input tile [W rows][128 ci] as float4
        for (int i = j; i < W * 32; i += 128) {
            int r = i >> 5, q = (i & 31) << 2;
            int p = refl(base + r, TINv);
            *(float4*)(&sx[(r << 7) + q]) =
                *(const float4*)(xin + ((size_t)(b * TINv + p)) * CCH + cc + q);
        }
        __syncthreads();
        for (int ci = 0; ci < 128; ci++) {
            const float* wb = wt + ((size_t)(cc + ci) * KW) * CCH + c0;
#pragma unroll
            for (int k = 0; k < KW; k++) {
                float4 w = *(const float4*)(wb + k * CCH);
#pragma unroll
                for (int tt = 0; tt < TT; tt++) {
                    float v = sx[(S * tt + k) * 128 + ci];
                    acc[0][tt] = fmaf(w.x, v, acc[0][tt]);
                    acc[1][tt] = fmaf(w.y, v, acc[1][tt]);
                    acc[2][tt] = fmaf(w.z, v, acc[2][tt]);
                    acc[3][tt] = fmaf(w.w, v, acc[3][tt]);
                }
            }
        }
    }
    float4 g = *(const float4*)(nw + c0);
    float4 e = *(const float4*)(nb + c0);
    for (int tt = 0; tt < TT; tt++) {
        float s1 = acc[0][tt] + acc[1][tt] + acc[2][tt] + acc[3][tt];
        float s2 = acc[0][tt] * acc[0][tt] + acc[1][tt] * acc[1][tt] +
                   acc[2][tt] * acc[2][tt] + acc[3][tt] * acc[3][tt];
        float2 s = block_reduce2(s1, s2, sred);
        float mean = s.x * (1.f / 512.f);
        float var  = (s.y - s.x * s.x * (1.f / 512.f)) * (1.f / 511.f);
        float inv  = rsqrtf(var + 1e-5f);
        float4 o;
        o.x = fmaxf((acc[0][tt] - mean) * inv * g.x + e.x, 0.f);
        o.y = fmaxf((acc[1][tt] - mean) * inv * g.y + e.y, 0.f);
        o.z = fmaxf((acc[2][tt] - mean) * inv * g.z + e.z, 0.f);
        o.w = fmaxf((acc[3][tt] - mean) * inv * g.w + e.w, 0.f);
        *(float4*)(out + ((size_t)(b * TOUTv + t0 + tt)) * CCH + c0) = o;
    }
}

// ---------------------------------------------------------------------------
// Tiled fp32 GEMM (128x128x8, 8x8 per thread) + bias + exact GELU epilogue.
// Register-prefetch double buffer hides gmem latency behind compute.
// C[M,N] = gelu(A[M,K] @ B[K,N] + bias)
// ---------------------------------------------------------------------------
__global__ __launch_bounds__(256, 2) void k_gemm_gelu(
    const float* __restrict__ A, const float* __restrict__ Bm,
    const float* __restrict__ bias, float* __restrict__ Cm,
    int M, int N, int K) {
    __shared__ float As[8][128];
    __shared__ float Bs[8][128];
    int tid = threadIdx.x;
    int tx = tid & 15, ty = tid >> 4;
    const float* Ab = A + (size_t)blockIdx.y * 128 * K;
    const float* Bb = Bm + blockIdx.x * 128;
    float acc[8][8];
#pragma unroll
    for (int i = 0; i < 8; i++)
#pragma unroll
        for (int jj = 0; jj < 8; jj++) acc[i][jj] = 0.f;
    int arow = tid >> 1, acol = (tid & 1) * 4;
    int brow = tid >> 5, bcol = (tid & 31) * 4;
    const float* aptr = Ab + (size_t)arow * K + acol;
    const float* bptr = Bb + (size_t)brow * N + bcol;
    float4 av = *(const float4*)(aptr);
    float4 bv = *(const float4*)(bptr);
    for (int k0 = 0; k0 < K; k0 += 8) {
        __syncthreads();
        As[acol + 0][arow] = av.x;
        As[acol + 1][arow] = av.y;
        As[acol + 2][arow] = av.z;
        As[acol + 3][arow] = av.w;
        *(float4*)(&Bs[brow][bcol]) = bv;
        __syncthreads();
        if (k0 + 8 < K) {  // prefetch next tile while computing this one
            av = *(const float4*)(aptr + k0 + 8);
            bv = *(const float4*)(bptr + (size_t)(k0 + 8) * N);
        }
#pragma unroll
        for (int kk = 0; kk < 8; kk++) {
            float a[8], bb[8];
            *(float4*)(a)      = *(const float4*)(&As[kk][ty * 8]);
            *(float4*)(a + 4)  = *(const float4*)(&As[kk][ty * 8 + 4]);
            *(float4*)(bb)     = *(const float4*)(&Bs[kk][tx * 8]);
            *(float4*)(bb + 4) = *(const float4*)(&Bs[kk][tx * 8 + 4]);
#pragma unroll
            for (int i = 0; i < 8; i++)
#pragma unroll
                for (int jj = 0; jj < 8; jj++)
                    acc[i][jj] = fmaf(a[i], bb[jj], acc[i][jj]);
        }
    }
    int m0 = blockIdx.y * 128 + ty * 8, n0 = blockIdx.x * 128 + tx * 8;
    float bv8[8];
#pragma unroll
    for (int jj = 0; jj < 8; jj++) bv8[jj] = bias[n0 + jj];
#pragma unroll
    for (int i = 0; i < 8; i++) {
#pragma unroll
        for (int jj = 0; jj < 8; jj++) acc[i][jj] = gelu_exact(acc[i][jj] + bv8[jj]);
        *(float4*)(Cm + (size_t)(m0 + i) * N + n0) =
            make_float4(acc[i][0], acc[i][1], acc[i][2], acc[i][3]);
        *(float4*)(Cm + (size_t)(m0 + i) * N + n0 + 4) =
            make_float4(acc[i][4], acc[i][5], acc[i][6], acc[i][7]);
    }
}

// ---------------------------------------------------------------------------
// MLP head: imp = sigmoid(z2 @ w3 + b3) + 1e-5.  One warp per row.
// ---------------------------------------------------------------------------
__global__ __launch_bounds__(256) void k_mlp3(
    const float* __restrict__ z2, const float* __restrict__ w3,
    const float* __restrict__ b3, float* __restrict__ imp) {
    int row = blockIdx.x * 8 + (threadIdx.x >> 5);
    int lane = threadIdx.x & 31;
    const float* zr = z2 + (size_t)row * DMLP;
    float s = 0.f;
    for (int i = lane; i < DMLP; i += 32) s = fmaf(zr[i], w3[i], s);
#pragma unroll
    for (int o = 16; o > 0; o >>= 1) s += __shfl_down_sync(0xffffffffu, s, o);
    if (lane == 0) imp[row] = 1.f / (1.f + expf(-(s + b3[0]))) + 1e-5f;
}

// ---------------------------------------------------------------------------
// Normalize importance + inclusive cumsum. One block per batch (512 threads).
// ---------------------------------------------------------------------------
__global__ __launch_bounds__(512) void k_scan(const float* __restrict__ imp,
                                              float* __restrict__ cs) {
    __shared__ float sa[512], sb[512];
    int b = blockIdx.x, t = threadIdx.x;
    sa[t] = imp[b * T3 + t];
    __syncthreads();
    float* src = sa;
    float* dst = sb;
    for (int off = 1; off < 512; off <<= 1) {
        float v = src[t] + ((t >= off) ? src[t - off] : 0.f);
        dst[t] = v;
        __syncthreads();
        float* tmp = src; src = dst; dst = tmp;
    }
    float scale = 256.f / src[511];
    cs[b * T3 + t] = src[t] * scale;
}

// ---------------------------------------------------------------------------
// Smartpool warp + final ChannelNorm + ReLU.
// grid (TN, B), block 512 (one thread per channel). Output [B][C][TN].
// ---------------------------------------------------------------------------
__global__ __launch_bounds__(512) void k_pool(
    const float* __restrict__ f, const float* __restrict__ cs,
    const float* __restrict__ nw, const float* __restrict__ nb,
    float* __restrict__ out) {
    __shared__ float scs[513];
    __shared__ float sred[64];
    int b = blockIdx.y, n = blockIdx.x, c = threadIdx.x;
    if (c == 0) scs[0] = 0.f;
    scs[c + 1] = cs[b * T3 + c];
    __syncthreads();
    float fn = (float)n;
    bool lastn = (n == TN - 1);
    int lo;
    {
        int a = 0, e = 512;
        while (a < e) { int m = (a + e) >> 1; if (scs[m + 1] > fn) e = m; else a = m + 1; }
        lo = a;
    }
    int hi = 512;
    if (!lastn) {
        int a = 0, e = 512;
        while (a < e) { int m = (a + e) >> 1; if (scs[m] < fn + 1.f) a = m + 1; else e = m; }
        hi = a;
    }
    float acc = 0.f;
    for (int t = lo; t < hi; t++) {
        float x1 = scs[t + 1] - fn, x0 = scs[t] - fn;
        float d1 = lastn ? fmaxf(x1, 0.f) : fminf(fmaxf(x1, 0.f), 1.f);
        float d0 = lastn ? fmaxf(x0, 0.f) : fminf(fmaxf(x0, 0.f), 1.f);
        acc = fmaf(d1 - d0, f[((size_t)(b * T3 + t)) * CCH + c], acc);
    }
    float2 s = block_reduce2(acc, acc * acc, sred);
    float mean = s.x * (1.f / 512.f);
    float var  = (s.y - s.x * s.x * (1.f / 512.f)) * (1.f / 511.f);
    float inv  = rsqrtf(var + 1e-5f);
    float v    = (acc - mean) * inv * nw[c] + nb[c];
    out[((size_t)(b * CCH + c)) * TN + n] = fmaxf(v, 0.f);
}

// ---------------------------------------------------------------------------
// Launch
// ---------------------------------------------------------------------------
extern "C" void kernel_launch(void* const* d_in, const int* in_sizes, int n_in,
                              void* d_out, int out_size) {
    (void)in_sizes; (void)n_in; (void)out_size;
    const float* x   = (const float*)d_in[0];
    const float* c0w = (const float*)d_in[1];
    const float* c0b = (const float*)d_in[2];
    const float* c1w = (const float*)d_in[3];
    const float* c1b = (const float*)d_in[4];
    const float* c2w = (const float*)d_in[5];
    const float* c2b = (const float*)d_in[6];
    const float* c3w = (const float*)d_in[7];
    const float* c3b = (const float*)d_in[8];
    const float* w1  = (const float*)d_in[9];
    const float* b1  = (const float*)d_in[10];
    const float* w2  = (const float*)d_in[11];
    const float* b2  = (const float*)d_in[12];
    const float* w3  = (const float*)d_in[13];
    const float* b3  = (const float*)d_in[14];
    const float* n0w = (const float*)d_in[15];
    const float* n0b = (const float*)d_in[16];
    const float* n1w = (const float*)d_in[17];
    const float* n1b = (const float*)d_in[18];
    const float* n2w = (const float*)d_in[19];
    const float* n2b = (const float*)d_in[20];
    const float* n3w = (const float*)d_in[21];
    const float* n3b = (const float*)d_in[22];
    const float* n4w = (const float*)d_in[23];
    const float* n4b = (const float*)d_in[24];
    float* out = (float*)d_out;

    float *p_h0, *p_h1, *p_h2, *p_f, *p_z1, *p_z2, *p_imp, *p_cs;
    float *p_w0t, *p_w1t, *p_w2t, *p_w3t;
    cudaGetSymbolAddress((void**)&p_h0,  g_h0);
    cudaGetSymbolAddress((void**)&p_h1,  g_h1);
    cudaGetSymbolAddress((void**)&p_h2,  g_h2);
    cudaGetSymbolAddress((void**)&p_f,   g_f);
    cudaGetSymbolAddress((void**)&p_z1,  g_z1);
    cudaGetSymbolAddress((void**)&p_z2,  g_z2);
    cudaGetSymbolAddress((void**)&p_imp, g_imp);
    cudaGetSymbolAddress((void**)&p_cs,  g_cs);
    cudaGetSymbolAddress((void**)&p_w0t, g_w0t);
    cudaGetSymbolAddress((void**)&p_w1t, g_w1t);
    cudaGetSymbolAddress((void**)&p_w2t, g_w2t);
    cudaGetSymbolAddress((void**)&p_w3t, g_w3t);

    // weight transposes
    k_wtrans<<<(10 * CCH + 255) / 256, 256>>>(c0w, p_w0t, 1, 10, 10 * CCH);
    k_wtrans<<<(CCH * 8 * CCH) / 256, 256>>>(c1w, p_w1t, CCH, 8, CCH * 8 * CCH);
    k_wtrans<<<(CCH * 4 * CCH) / 256, 256>>>(c2w, p_w2t, CCH, 4, CCH * 4 * CCH);
    k_wtrans<<<(CCH * 4 * CCH) / 256, 256>>>(c3w, p_w3t, CCH, 4, CCH * 4 * CCH);

    // encoder
    k_conv0<<<dim3(T0 / 8, BATCH), 512>>>(x, p_w0t, c0b, n0w, n0b, p_h0);
    k_conv<8, 4, 2, 16><<<dim3(T1 / 16, BATCH), 128>>>(p_h0, T0, T1, p_w1t, c1b, n1w, n1b, p_h1);
    k_conv<4, 2, 1, 16><<<dim3(T2 / 16, BATCH), 128>>>(p_h1, T1, T2, p_w2t, c2b, n2w, n2b, p_h2);
    k_conv<4, 2, 1, 16><<<dim3(T3 / 16, BATCH), 128>>>(p_h2, T2, T3, p_w3t, c3b, n3w, n3b, p_f);

    // importance MLP
    k_gemm_gelu<<<dim3(DMLP / 128, (BATCH * T3) / 128), 256>>>(p_f, w1, b1, p_z1,
                                                               BATCH * T3, DMLP, CCH);
    k_gemm_gelu<<<dim3(DMLP / 128, (BATCH * T3) / 128), 256>>>(p_z1, w2, b2, p_z2,
                                                               BATCH * T3, DMLP, DMLP);
    k_mlp3<<<(BATCH * T3) / 8, 256>>>(p_z2, w3, b3, p_imp);
    k_scan<<<BATCH, 512>>>(p_imp, p_cs);

    // smartpool warp + final norm
    k_pool<<<dim3(TN, BATCH), 512>>>(p_f, p_cs, n4w, n4b, out);
}

// round 4
// speedup vs baseline: 1.6674x; 1.6674x over previous
#include <cuda_runtime.h>
#include <cuda_bf16.h>
#include <math.h>

// ---------------------------------------------------------------------------
// Problem constants
// ---------------------------------------------------------------------------
#define BATCH 4
#define LIN   40960
#define CCH   512
#define T0    8192
#define T1    2048
#define T2    1024
#define T3    512
#define TN    256
#define DMLP  2048

// ---------------------------------------------------------------------------
// Scratch (device globals; no allocation allowed)
// ---------------------------------------------------------------------------
__device__ float g_h0[BATCH * T0 * CCH];
__device__ float g_h1[BATCH * T1 * CCH];
__device__ float g_h2[BATCH * T2 * CCH];
__device__ float g_f [BATCH * T3 * CCH];
__device__ float g_z1[BATCH * T3 * DMLP];
__device__ float g_z2[BATCH * T3 * DMLP];
__device__ float g_imp[BATCH * T3];
__device__ float g_cs [BATCH * T3];
__device__ float g_w0t[10 * CCH];
__device__ float g_w1t[CCH * 8 * CCH];
__device__ float g_w2t[CCH * 4 * CCH];
__device__ float g_w3t[CCH * 4 * CCH];

// ---------------------------------------------------------------------------
// Helpers
// ---------------------------------------------------------------------------
__device__ __forceinline__ int refl(int p, int n) {
    return p < 0 ? -p : (p >= n ? 2 * n - 2 - p : p);
}

__device__ __forceinline__ float gelu_exact(float v) {
    return 0.5f * v * (1.f + erff(v * 0.70710678118654752f));
}

// Block-wide (sum, sumsq) reduction over whole block. sred >= 64 floats.
__device__ __forceinline__ float2 block_reduce2(float v1, float v2, float* sred) {
    __syncthreads();
    int lane = threadIdx.x & 31, wid = threadIdx.x >> 5;
    int nw = blockDim.x >> 5;
#pragma unroll
    for (int o = 16; o > 0; o >>= 1) {
        v1 += __shfl_down_sync(0xffffffffu, v1, o);
        v2 += __shfl_down_sync(0xffffffffu, v2, o);
    }
    if (lane == 0) { sred[wid] = v1; sred[wid + 32] = v2; }
    __syncthreads();
    if (wid == 0) {
        v1 = (lane < nw) ? sred[lane] : 0.f;
        v2 = (lane < nw) ? sred[lane + 32] : 0.f;
#pragma unroll
        for (int o = 16; o > 0; o >>= 1) {
            v1 += __shfl_down_sync(0xffffffffu, v1, o);
            v2 += __shfl_down_sync(0xffffffffu, v2, o);
        }
        if (lane == 0) { sred[0] = v1; sred[32] = v2; }
    }
    __syncthreads();
    return make_float2(sred[0], sred[32]);
}

// ---------------------------------------------------------------------------
// Weight transpose: w[c][ci][k] -> wt[(ci*KW+k)*512 + c]
// ---------------------------------------------------------------------------
__global__ void k_wtrans(const float* __restrict__ w, float* __restrict__ wt,
                         int CI, int KW, int total) {
    int idx = blockIdx.x * blockDim.x + threadIdx.x;
    if (idx < total) {
        int ck = CI * KW;
        int c = idx / ck;
        int r = idx - c * ck;
        wt[r * CCH + c] = w[idx];
    }
}

// ---------------------------------------------------------------------------
// conv0 (1->512, k=10, s=5, reflect pad 3) + ChannelNorm + ReLU
// ---------------------------------------------------------------------------
__global__ __launch_bounds__(512) void k_conv0(
    const float* __restrict__ x, const float* __restrict__ w0t,
    const float* __restrict__ bias, const float* __restrict__ nw,
    const float* __restrict__ nb, float* __restrict__ out) {
    const int TT = 8, KW = 10, S = 5, PAD = 3;
    const int W = S * (TT - 1) + KW;  // 45
    __shared__ float sx[48];
    __shared__ float sred[64];
    int b = blockIdx.y, t0 = blockIdx.x * TT, c = threadIdx.x;
    if (c < W) {
        int p = refl(S * t0 - PAD + c, LIN);
        sx[c] = x[b * LIN + p];
    }
    __syncthreads();
    float acc[TT];
    float bi = bias[c];
#pragma unroll
    for (int tt = 0; tt < TT; tt++) acc[tt] = bi;
#pragma unroll
    for (int k = 0; k < KW; k++) {
        float w = w0t[k * CCH + c];
#pragma unroll
        for (int tt = 0; tt < TT; tt++) acc[tt] = fmaf(w, sx[S * tt + k], acc[tt]);
    }
    float gw = nw[c], gb = nb[c];
    for (int tt = 0; tt < TT; tt++) {
        float2 s = block_reduce2(acc[tt], acc[tt] * acc[tt], sred);
        float mean = s.x * (1.f / 512.f);
        float var  = (s.y - s.x * s.x * (1.f / 512.f)) * (1.f / 511.f);
        float inv  = rsqrtf(var + 1e-5f);
        float v    = (acc[tt] - mean) * inv * gw + gb;
        out[((size_t)(b * T0 + t0 + tt)) * CCH + c] = fmaxf(v, 0.f);
    }
}

// ---------------------------------------------------------------------------
// Fused conv (512->512) + ChannelNorm + ReLU.
// Block = NG groups of 128 threads. Group g owns time-steps 8g..8g+7.
// Thread covers 4 channels (c0 = 4*(tid&127)); per input channel ci, the
// input window is loaded into registers (broadcast LDS), then 8*KW*4 FFMA.
// ---------------------------------------------------------------------------
template <int KW, int S, int PAD, int NG>
__global__ __launch_bounds__(NG * 128) void k_conv(
    const float* __restrict__ xin, int TINv, int TOUTv,
    const float* __restrict__ wt, const float* __restrict__ bias,
    const float* __restrict__ nw, const float* __restrict__ nb,
    float* __restrict__ out) {
    constexpr int TT = 8 * NG;
    constexpr int W  = S * (TT - 1) + KW;   // block window
    constexpr int WG = S * 7 + KW;          // per-group window
    __shared__ float sx[W * 128];
    __shared__ float sred[NG * 64];
    int b = blockIdx.y, t0 = blockIdx.x * TT;
    int j = threadIdx.x;
    int g = j >> 7;            // group id
    int jg = j & 127;          // thread-in-group
    int c0 = jg * 4;
    int roff = 8 * S * g;      // group window row offset

    float acc[4][8];
    float4 bi = *(const float4*)(bias + c0);
#pragma unroll
    for (int tt = 0; tt < 8; tt++) {
        acc[0][tt] = bi.x; acc[1][tt] = bi.y; acc[2][tt] = bi.z; acc[3][tt] = bi.w;
    }
    int base = S * t0 - PAD;
    for (int cc = 0; cc < CCH; cc += 128) {
        __syncthreads();
        for (int i = j; i < W * 32; i += NG * 128) {
            int r = i >> 5, q = (i & 31) << 2;
            int p = refl(base + r, TINv);
            *(float4*)(&sx[(r << 7) + q]) =
                *(const float4*)(xin + ((size_t)(b * TINv + p)) * CCH + cc + q);
        }
        __syncthreads();
        for (int ci = 0; ci < 128; ci++) {
            float win[WG];
#pragma unroll
            for (int r = 0; r < WG; r++) win[r] = sx[(roff + r) * 128 + ci];
            const float* wb = wt + ((size_t)(cc + ci) * KW) * CCH + c0;
#pragma unroll
            for (int k = 0; k < KW; k++) {
                float4 w = *(const float4*)(wb + k * CCH);
#pragma unroll
                for (int tt = 0; tt < 8; tt++) {
                    float v = win[S * tt + k];
                    acc[0][tt] = fmaf(w.x, v, acc[0][tt]);
                    acc[1][tt] = fmaf(w.y, v, acc[1][tt]);
                    acc[2][tt] = fmaf(w.z, v, acc[2][tt]);
                    acc[3][tt] = fmaf(w.w, v, acc[3][tt]);
                }
            }
        }
    }
    // group-local ChannelNorm (each group holds all 512 channels of its tt's)
    float4 gg = *(const float4*)(nw + c0);
    float4 ee = *(const float4*)(nb + c0);
    float* sg = sred + g * 64;
    int lane = j & 31, wig = (j >> 5) & 3;
    for (int tt = 0; tt < 8; tt++) {
        float v1 = acc[0][tt] + acc[1][tt] + acc[2][tt] + acc[3][tt];
        float v2 = acc[0][tt] * acc[0][tt] + acc[1][tt] * acc[1][tt] +
                   acc[2][tt] * acc[2][tt] + acc[3][tt] * acc[3][tt];
        __syncthreads();
#pragma unroll
        for (int o = 16; o > 0; o >>= 1) {
            v1 += __shfl_down_sync(0xffffffffu, v1, o);
            v2 += __shfl_down_sync(0xffffffffu, v2, o);
        }
        if (lane == 0) { sg[wig] = v1; sg[wig + 32] = v2; }
        __syncthreads();
        float s1 = sg[0] + sg[1] + sg[2] + sg[3];
        float s2 = sg[32] + sg[33] + sg[34] + sg[35];
        float mean = s1 * (1.f / 512.f);
        float var  = (s2 - s1 * s1 * (1.f / 512.f)) * (1.f / 511.f);
        float inv  = rsqrtf(var + 1e-5f);
        float4 o;
        o.x = fmaxf((acc[0][tt] - mean) * inv * gg.x + ee.x, 0.f);
        o.y = fmaxf((acc[1][tt] - mean) * inv * gg.y + ee.y, 0.f);
        o.z = fmaxf((acc[2][tt] - mean) * inv * gg.z + ee.z, 0.f);
        o.w = fmaxf((acc[3][tt] - mean) * inv * gg.w + ee.w, 0.f);
        int t = t0 + g * 8 + tt;
        *(float4*)(out + ((size_t)(b * TOUTv + t)) * CCH + c0) = o;
    }
}

// ---------------------------------------------------------------------------
// Tiled fp32 GEMM (128x128x8, 8x8 per thread) + bias + exact GELU epilogue.
// Register-prefetch double buffer hides gmem latency behind compute.
// ---------------------------------------------------------------------------
__global__ __launch_bounds__(256) void k_gemm_gelu(
    const float* __restrict__ A, const float* __restrict__ Bm,
    const float* __restrict__ bias, float* __restrict__ Cm,
    int M, int N, int K) {
    __shared__ float As[8][128];
    __shared__ float Bs[8][128];
    int tid = threadIdx.x;
    int tx = tid & 15, ty = tid >> 4;
    const float* Ab = A + (size_t)blockIdx.y * 128 * K;
    const float* Bb = Bm + blockIdx.x * 128;
    float acc[8][8];
#pragma unroll
    for (int i = 0; i < 8; i++)
#pragma unroll
        for (int jj = 0; jj < 8; jj++) acc[i][jj] = 0.f;
    int arow = tid >> 1, acol = (tid & 1) * 4;
    int brow = tid >> 5, bcol = (tid & 31) * 4;
    const float* aptr = Ab + (size_t)arow * K + acol;
    const float* bptr = Bb + (size_t)brow * N + bcol;
    float4 av = *(const float4*)(aptr);
    float4 bv = *(const float4*)(bptr);
    for (int k0 = 0; k0 < K; k0 += 8) {
        __syncthreads();
        As[acol + 0][arow] = av.x;
        As[acol + 1][arow] = av.y;
        As[acol + 2][arow] = av.z;
        As[acol + 3][arow] = av.w;
        *(float4*)(&Bs[brow][bcol]) = bv;
        __syncthreads();
        if (k0 + 8 < K) {
            av = *(const float4*)(aptr + k0 + 8);
            bv = *(const float4*)(bptr + (size_t)(k0 + 8) * N);
        }
#pragma unroll
        for (int kk = 0; kk < 8; kk++) {
            float a[8], bb[8];
            *(float4*)(a)      = *(const float4*)(&As[kk][ty * 8]);
            *(float4*)(a + 4)  = *(const float4*)(&As[kk][ty * 8 + 4]);
            *(float4*)(bb)     = *(const float4*)(&Bs[kk][tx * 8]);
            *(float4*)(bb + 4) = *(const float4*)(&Bs[kk][tx * 8 + 4]);
#pragma unroll
            for (int i = 0; i < 8; i++)
#pragma unroll
                for (int jj = 0; jj < 8; jj++)
                    acc[i][jj] = fmaf(a[i], bb[jj], acc[i][jj]);
        }
    }
    int m0 = blockIdx.y * 128 + ty * 8, n0 = blockIdx.x * 128 + tx * 8;
    float bv8[8];
#pragma unroll
    for (int jj = 0; jj < 8; jj++) bv8[jj] = bias[n0 + jj];
#pragma unroll
    for (int i = 0; i < 8; i++) {
#pragma unroll
        for (int jj = 0; jj < 8; jj++) acc[i][jj] = gelu_exact(acc[i][jj] + bv8[jj]);
        *(float4*)(Cm + (size_t)(m0 + i) * N + n0) =
            make_float4(acc[i][0], acc[i][1], acc[i][2], acc[i][3]);
        *(float4*)(Cm + (size_t)(m0 + i) * N + n0 + 4) =
            make_float4(acc[i][4], acc[i][5], acc[i][6], acc[i][7]);
    }
}

// ---------------------------------------------------------------------------
// MLP head: imp = sigmoid(z2 @ w3 + b3) + 1e-5.  One warp per row.
// ---------------------------------------------------------------------------
__global__ __launch_bounds__(256) void k_mlp3(
    const float* __restrict__ z2, const float* __restrict__ w3,
    const float* __restrict__ b3, float* __restrict__ imp) {
    int row = blockIdx.x * 8 + (threadIdx.x >> 5);
    int lane = threadIdx.x & 31;
    const float* zr = z2 + (size_t)row * DMLP;
    float s = 0.f;
    for (int i = lane; i < DMLP; i += 32) s = fmaf(zr[i], w3[i], s);
#pragma unroll
    for (int o = 16; o > 0; o >>= 1) s += __shfl_down_sync(0xffffffffu, s, o);
    if (lane == 0) imp[row] = 1.f / (1.f + expf(-(s + b3[0]))) + 1e-5f;
}

// ---------------------------------------------------------------------------
// Normalize importance + inclusive cumsum. One block per batch.
// ---------------------------------------------------------------------------
__global__ __launch_bounds__(512) void k_scan(const float* __restrict__ imp,
                                              float* __restrict__ cs) {
    __shared__ float sa[512], sb[512];
    int b = blockIdx.x, t = threadIdx.x;
    sa[t] = imp[b * T3 + t];
    __syncthreads();
    float* src = sa;
    float* dst = sb;
    for (int off = 1; off < 512; off <<= 1) {
        float v = src[t] + ((t >= off) ? src[t - off] : 0.f);
        dst[t] = v;
        __syncthreads();
        float* tmp = src; src = dst; dst = tmp;
    }
    float scale = 256.f / src[511];
    cs[b * T3 + t] = src[t] * scale;
}

// ---------------------------------------------------------------------------
// Smartpool warp + final ChannelNorm + ReLU. Output [B][C][TN].
// ---------------------------------------------------------------------------
__global__ __launch_bounds__(512) void k_pool(
    const float* __restrict__ f, const float* __restrict__ cs,
    const float* __restrict__ nw, const float* __restrict__ nb,
    float* __restrict__ out) {
    __shared__ float scs[513];
    __shared__ float sred[64];
    int b = blockIdx.y, n = blockIdx.x, c = threadIdx.x;
    if (c == 0) scs[0] = 0.f;
    scs[c + 1] = cs[b * T3 + c];
    __syncthreads();
    float fn = (float)n;
    bool lastn = (n == TN - 1);
    int lo;
    {
        int a = 0, e = 512;
        while (a < e) { int m = (a + e) >> 1; if (scs[m + 1] > fn) e = m; else a = m + 1; }
        lo = a;
    }
    int hi = 512;
    if (!lastn) {
        int a = 0, e = 512;
        while (a < e) { int m = (a + e) >> 1; if (scs[m] < fn + 1.f) a = m + 1; else e = m; }
        hi = a;
    }
    float acc = 0.f;
    for (int t = lo; t < hi; t++) {
        float x1 = scs[t + 1] - fn, x0 = scs[t] - fn;
        float d1 = lastn ? fmaxf(x1, 0.f) : fminf(fmaxf(x1, 0.f), 1.f);
        float d0 = lastn ? fmaxf(x0, 0.f) : fminf(fmaxf(x0, 0.f), 1.f);
        acc = fmaf(d1 - d0, f[((size_t)(b * T3 + t)) * CCH + c], acc);
    }
    float2 s = block_reduce2(acc, acc * acc, sred);
    float mean = s.x * (1.f / 512.f);
    float var  = (s.y - s.x * s.x * (1.f / 512.f)) * (1.f / 511.f);
    float inv  = rsqrtf(var + 1e-5f);
    float v    = (acc - mean) * inv * nw[c] + nb[c];
    out[((size_t)(b * CCH + c)) * TN + n] = fmaxf(v, 0.f);
}

// ---------------------------------------------------------------------------
// Launch (ordered so conv1 is launch index 5 -> captured by ncu -s 5 -c 1)
// ---------------------------------------------------------------------------
extern "C" void kernel_launch(void* const* d_in, const int* in_sizes, int n_in,
                              void* d_out, int out_size) {
    (void)in_sizes; (void)n_in; (void)out_size;
    const float* x   = (const float*)d_in[0];
    const float* c0w = (const float*)d_in[1];
    const float* c0b = (const float*)d_in[2];
    const float* c1w = (const float*)d_in[3];
    const float* c1b = (const float*)d_in[4];
    const float* c2w = (const float*)d_in[5];
    const float* c2b = (const float*)d_in[6];
    const float* c3w = (const float*)d_in[7];
    const float* c3b = (const float*)d_in[8];
    const float* w1  = (const float*)d_in[9];
    const float* b1  = (const float*)d_in[10];
    const float* w2  = (const float*)d_in[11];
    const float* b2  = (const float*)d_in[12];
    const float* w3  = (const float*)d_in[13];
    const float* b3  = (const float*)d_in[14];
    const float* n0w = (const float*)d_in[15];
    const float* n0b = (const float*)d_in[16];
    const float* n1w = (const float*)d_in[17];
    const float* n1b = (const float*)d_in[18];
    const float* n2w = (const float*)d_in[19];
    const float* n2b = (const float*)d_in[20];
    const float* n3w = (const float*)d_in[21];
    const float* n3b = (const float*)d_in[22];
    const float* n4w = (const float*)d_in[23];
    const float* n4b = (const float*)d_in[24];
    float* out = (float*)d_out;

    float *p_h0, *p_h1, *p_h2, *p_f, *p_z1, *p_z2, *p_imp, *p_cs;
    float *p_w0t, *p_w1t, *p_w2t, *p_w3t;
    cudaGetSymbolAddress((void**)&p_h0,  g_h0);
    cudaGetSymbolAddress((void**)&p_h1,  g_h1);
    cudaGetSymbolAddress((void**)&p_h2,  g_h2);
    cudaGetSymbolAddress((void**)&p_f,   g_f);
    cudaGetSymbolAddress((void**)&p_z1,  g_z1);
    cudaGetSymbolAddress((void**)&p_z2,  g_z2);
    cudaGetSymbolAddress((void**)&p_imp, g_imp);
    cudaGetSymbolAddress((void**)&p_cs,  g_cs);
    cudaGetSymbolAddress((void**)&p_w0t, g_w0t);
    cudaGetSymbolAddress((void**)&p_w1t, g_w1t);
    cudaGetSymbolAddress((void**)&p_w2t, g_w2t);
    cudaGetSymbolAddress((void**)&p_w3t, g_w3t);

    // launches 0..4
    k_wtrans<<<(10 * CCH + 255) / 256, 256>>>(c0w, p_w0t, 1, 10, 10 * CCH);
    k_conv0<<<dim3(T0 / 8, BATCH), 512>>>(x, p_w0t, c0b, n0w, n0b, p_h0);
    k_wtrans<<<(CCH * 8 * CCH) / 256, 256>>>(c1w, p_w1t, CCH, 8, CCH * 8 * CCH);
    k_wtrans<<<(CCH * 4 * CCH) / 256, 256>>>(c2w, p_w2t, CCH, 4, CCH * 4 * CCH);
    k_wtrans<<<(CCH * 4 * CCH) / 256, 256>>>(c3w, p_w3t, CCH, 4, CCH * 4 * CCH);

    // launch 5 -> ncu capture target: conv1
    k_conv<8, 4, 2, 2><<<dim3(T1 / 16, BATCH), 256>>>(p_h0, T0, T1, p_w1t, c1b, n1w, n1b, p_h1);
    k_conv<4, 2, 1, 2><<<dim3(T2 / 16, BATCH), 256>>>(p_h1, T1, T2, p_w2t, c2b, n2w, n2b, p_h2);
    k_conv<4, 2, 1, 1><<<dim3(T3 / 8,  BATCH), 128>>>(p_h2, T2, T3, p_w3t, c3b, n3w, n3b, p_f);

    // importance MLP
    k_gemm_gelu<<<dim3(DMLP / 128, (BATCH * T3) / 128), 256>>>(p_f, w1, b1, p_z1,
                                                               BATCH * T3, DMLP, CCH);
    k_gemm_gelu<<<dim3(DMLP / 128, (BATCH * T3) / 128), 256>>>(p_z1, w2, b2, p_z2,
                                                               BATCH * T3, DMLP, DMLP);
    k_mlp3<<<(BATCH * T3) / 8, 256>>>(p_z2, w3, b3, p_imp);
    k_scan<<<BATCH, 512>>>(p_imp, p_cs);

    // smartpool warp + final norm
    k_pool<<<dim3(TN, BATCH), 512>>>(p_f, p_cs, n4w, n4b, out);
}

// round 8
// speedup vs baseline: 5.6475x; 3.3871x over previous
#include <cuda_runtime.h>
#include <cuda_bf16.h>
#include <math.h>
#include <stdint.h>

// ---------------------------------------------------------------------------
// Problem constants
// ---------------------------------------------------------------------------
#define BATCH 4
#define LIN   40960
#define CCH   512
#define T0    8192
#define T1    2048
#define T2    1024
#define T3    512
#define TN    256
#define DMLP  2048

// ---------------------------------------------------------------------------
// Scratch (device globals; no allocation allowed)
// ---------------------------------------------------------------------------
__device__ __nv_bfloat16 g_h0h[BATCH * T0 * CCH], g_h0l[BATCH * T0 * CCH];
__device__ __nv_bfloat16 g_h1h[BATCH * T1 * CCH], g_h1l[BATCH * T1 * CCH];
__device__ __nv_bfloat16 g_h2h[BATCH * T2 * CCH], g_h2l[BATCH * T2 * CCH];
__device__ __nv_bfloat16 g_fh [BATCH * T3 * CCH], g_fl [BATCH * T3 * CCH];
__device__ __nv_bfloat16 g_z1h[BATCH * T3 * DMLP], g_z1l[BATCH * T3 * DMLP];
__device__ float g_f  [BATCH * T3 * CCH];
__device__ float g_z2 [BATCH * T3 * DMLP];
__device__ float g_raw[BATCH * T1 * CCH];
__device__ float g_imp[BATCH * T3];
__device__ float g_cs [BATCH * T3];
__device__ __nv_bfloat16 g_w1h[8 * CCH * CCH], g_w1l[8 * CCH * CCH];
__device__ __nv_bfloat16 g_w2h[4 * CCH * CCH], g_w2l[4 * CCH * CCH];
__device__ __nv_bfloat16 g_w3h[4 * CCH * CCH], g_w3l[4 * CCH * CCH];
__device__ __nv_bfloat16 g_mw1h[CCH * DMLP],   g_mw1l[CCH * DMLP];
__device__ __nv_bfloat16 g_mw2h[DMLP * DMLP],  g_mw2l[DMLP * DMLP];
__device__ float g_w0f[10 * CCH];

// ---------------------------------------------------------------------------
// Helpers
// ---------------------------------------------------------------------------
__device__ __forceinline__ int refl(int p, int n) {
    return p < 0 ? -p : (p >= n ? 2 * n - 2 - p : p);
}

__device__ __forceinline__ float gelu_exact(float v) {
    return 0.5f * v * (1.f + erff(v * 0.70710678118654752f));
}

__device__ __forceinline__ void fsplit(float v, __nv_bfloat16& h, __nv_bfloat16& l) {
    h = __float2bfloat16(v);
    l = __float2bfloat16(v - __bfloat162float(h));
}

__device__ __forceinline__ void ldsm_x4(unsigned addr, unsigned* r) {
    asm volatile("ldmatrix.sync.aligned.m8n8.x4.shared.b16 {%0,%1,%2,%3}, [%4];"
                 : "=r"(r[0]), "=r"(r[1]), "=r"(r[2]), "=r"(r[3]) : "r"(addr));
}
__device__ __forceinline__ void ldsm_x2t(unsigned addr, unsigned* r) {
    asm volatile("ldmatrix.sync.aligned.m8n8.x2.trans.shared.b16 {%0,%1}, [%2];"
                 : "=r"(r[0]), "=r"(r[1]) : "r"(addr));
}
__device__ __forceinline__ void mma16816(float* d, const unsigned* a, const unsigned* b) {
    asm volatile(
        "mma.sync.aligned.m16n8k16.row.col.f32.bf16.bf16.f32 "
        "{%0,%1,%2,%3},{%4,%5,%6,%7},{%8,%9},{%0,%1,%2,%3};"
        : "+f"(d[0]), "+f"(d[1]), "+f"(d[2]), "+f"(d[3])
        : "r"(a[0]), "r"(a[1]), "r"(a[2]), "r"(a[3]), "r"(b[0]), "r"(b[1]));
}

// Block-wide (sum, sumsq) reduction. sred >= 64 floats.
__device__ __forceinline__ float2 block_reduce2(float v1, float v2, float* sred) {
    __syncthreads();
    int lane = threadIdx.x & 31, wid = threadIdx.x >> 5;
    int nw = blockDim.x >> 5;
#pragma unroll
    for (int o = 16; o > 0; o >>= 1) {
        v1 += __shfl_down_sync(0xffffffffu, v1, o);
        v2 += __shfl_down_sync(0xffffffffu, v2, o);
    }
    if (lane == 0) { sred[wid] = v1; sred[wid + 32] = v2; }
    __syncthreads();
    if (wid == 0) {
        v1 = (lane < nw) ? sred[lane] : 0.f;
        v2 = (lane < nw) ? sred[lane + 32] : 0.f;
#pragma unroll
        for (int o = 16; o > 0; o >>= 1) {
            v1 += __shfl_down_sync(0xffffffffu, v1, o);
            v2 += __shfl_down_sync(0xffffffffu, v2, o);
        }
        if (lane == 0) { sred[0] = v1; sred[32] = v2; }
    }
    __syncthreads();
    return make_float2(sred[0], sred[32]);
}

// ---------------------------------------------------------------------------
// Weight prep
// ---------------------------------------------------------------------------
// conv weights w[c][ci][tap] -> split bf16 at [(tap*CI+ci)][c]  (K tap-major)
__global__ void k_wsplit_conv(const float* __restrict__ w,
                              __nv_bfloat16* __restrict__ wh,
                              __nv_bfloat16* __restrict__ wl,
                              int CI, int KW, int total) {
    int idx = blockIdx.x * blockDim.x + threadIdx.x;
    if (idx >= total) return;
    int ck = CI * KW;
    int c = idx / ck, rem = idx - c * ck;
    int ci = rem / KW, tap = rem - ci * KW;
    __nv_bfloat16 h, l;
    fsplit(w[idx], h, l);
    int o = (tap * CI + ci) * CCH + c;
    wh[o] = h; wl[o] = l;
}

// plain elementwise split (row-major [K][N] kept)
__global__ void k_split(const float* __restrict__ src,
                        __nv_bfloat16* __restrict__ h,
                        __nv_bfloat16* __restrict__ l, int total) {
    int idx = blockIdx.x * blockDim.x + threadIdx.x;
    if (idx >= total) return;
    __nv_bfloat16 hh, ll;
    fsplit(src[idx], hh, ll);
    h[idx] = hh; l[idx] = ll;
}

// conv0 weight transpose w[c][0][k] -> w0f[k*512+c]
__global__ void k_w0trans(const float* __restrict__ w, float* __restrict__ wt) {
    int idx = blockIdx.x * blockDim.x + threadIdx.x;
    if (idx < 10 * CCH) {
        int c = idx / 10, k = idx - c * 10;
        wt[k * CCH + c] = w[idx];
    }
}

// ---------------------------------------------------------------------------
// conv0 (1->512, k=10, s=5, reflect pad 3) + ChannelNorm + ReLU -> bf16 split
// ---------------------------------------------------------------------------
__global__ __launch_bounds__(512) void k_conv0(
    const float* __restrict__ x, const float* __restrict__ w0t,
    const float* __restrict__ bias, const float* __restrict__ nw,
    const float* __restrict__ nb,
    __nv_bfloat16* __restrict__ oh, __nv_bfloat16* __restrict__ ol) {
    const int TT = 8, KW = 10, S = 5, PAD = 3;
    const int W = S * (TT - 1) + KW;  // 45
    __shared__ float sx[48];
    __shared__ float sred[64];
    int b = blockIdx.y, t0 = blockIdx.x * TT, c = threadIdx.x;
    if (c < W) {
        int p = refl(S * t0 - PAD + c, LIN);
        sx[c] = x[b * LIN + p];
    }
    __syncthreads();
    float acc[TT];
    float bi = bias[c];
#pragma unroll
    for (int tt = 0; tt < TT; tt++) acc[tt] = bi;
#pragma unroll
    for (int k = 0; k < KW; k++) {
        float w = w0t[k * CCH + c];
#pragma unroll
        for (int tt = 0; tt < TT; tt++) acc[tt] = fmaf(w, sx[S * tt + k], acc[tt]);
    }
    float gw = nw[c], gb = nb[c];
    for (int tt = 0; tt < TT; tt++) {
        float2 s = block_reduce2(acc[tt], acc[tt] * acc[tt], sred);
        float mean = s.x * (1.f / 512.f);
        float var  = (s.y - s.x * s.x * (1.f / 512.f)) * (1.f / 511.f);
        float inv  = rsqrtf(var + 1e-5f);
        float v    = fmaxf((acc[tt] - mean) * inv * gw + gb, 0.f);
        __nv_bfloat16 h, l;
        fsplit(v, h, l);
        size_t o = ((size_t)(b * T0 + t0 + tt)) * CCH + c;
        oh[o] = h; ol[o] = l;
    }
}

// ---------------------------------------------------------------------------
// Tensor-core split-bf16 GEMM with implicit im2col A-loader.
//   C[M,N] = A[M,K] * B[K,N];  A row t, k=(tap*512+ci) -> in[b][S*t-PAD+tap][ci]
//   (KW==1 -> plain GEMM)
// 3-pass: AhBh + AhBl + AlBh into fp32 acc.
// BM=128, BN=128, KT=32. 256 threads, 8 warps (2x4), warp tile 64x32.
// EPI: 0 raw fp32 -> outF;  1 bias+gelu fp32 -> outF;  2 bias+gelu -> split hi/lo
// ---------------------------------------------------------------------------
#define ASTR 40   // A smem row stride in bf16 (80B: conflict-free for ldmatrix)
#define BSTR 136  // B smem row stride in bf16 (272B: conflict-free)

#define TG_LOAD(KT_IDX)                                                      \
    {                                                                        \
        int kk0 = (KT_IDX) * 32;                                             \
        int tap = (KW == 1) ? 0 : (kk0 >> 9);                                \
        int ci0 = (KW == 1) ? kk0 : (kk0 & 511);                             \
        for (int i = 0; i < 2; i++) {                                        \
            int tt = t0m + am[i];                                            \
            int r = (KW == 1) ? tt : refl(S * tt - PAD + tap, TIN);          \
            size_t offA = (size_t)(bb * TIN + r) * astride + ci0 + akk;      \
            pah[i] = *(const uint4*)(AHi + offA);                            \
            pal[i] = *(const uint4*)(ALo + offA);                            \
            size_t offB = (size_t)(kk0 + bk[i]) * N + n0 + bnn;              \
            pbh[i] = *(const uint4*)(BHi + offB);                            \
            pbl[i] = *(const uint4*)(BLo + offB);                            \
        }                                                                    \
    }

template <int KW, int S, int PAD, int EPI>
__global__ __launch_bounds__(256, 1) void k_tgemm(
    const __nv_bfloat16* __restrict__ AHi, const __nv_bfloat16* __restrict__ ALo,
    const __nv_bfloat16* __restrict__ BHi, const __nv_bfloat16* __restrict__ BLo,
    const float* __restrict__ bias, float* __restrict__ outF,
    __nv_bfloat16* __restrict__ outHi, __nv_bfloat16* __restrict__ outLo,
    int TIN, int TOUT, int N, int K, int astride) {
    __shared__ __nv_bfloat16 sAh[128 * ASTR], sAl[128 * ASTR];
    __shared__ __nv_bfloat16 sBh[32 * BSTR], sBl[32 * BSTR];
    const int tid = threadIdx.x;
    const int n0 = blockIdx.x * 128;
    const int t0m = blockIdx.y * 128;
    const int bb = blockIdx.z;

    float acc[4][4][4];
#pragma unroll
    for (int mi = 0; mi < 4; mi++)
#pragma unroll
        for (int ni = 0; ni < 4; ni++)
#pragma unroll
            for (int q = 0; q < 4; q++) acc[mi][ni][q] = 0.f;

    uint4 pah[2], pal[2], pbh[2], pbl[2];
    const int am[2] = { (tid >> 2), (tid >> 2) + 64 };
    const int akk = (tid & 3) * 8;
    const int bk[2] = { (tid >> 4), (tid >> 4) + 16 };
    const int bnn = (tid & 15) * 8;

    const unsigned baseAh = (unsigned)__cvta_generic_to_shared(sAh);
    const unsigned baseAl = (unsigned)__cvta_generic_to_shared(sAl);
    const unsigned baseBh = (unsigned)__cvta_generic_to_shared(sBh);
    const unsigned baseBl = (unsigned)__cvta_generic_to_shared(sBl);

    const int warp = tid >> 5, lane = tid & 31;
    const int wm = warp >> 2, wn = warp & 3;
    const int lrow = lane & 15, lko = (lane >> 4) * 8;

    const int NKT = K / 32;
    TG_LOAD(0)
    for (int kt = 0; kt < NKT; kt++) {
        __syncthreads();
#pragma unroll
        for (int i = 0; i < 2; i++) {
            *(uint4*)&sAh[am[i] * ASTR + akk] = pah[i];
            *(uint4*)&sAl[am[i] * ASTR + akk] = pal[i];
            *(uint4*)&sBh[bk[i] * BSTR + bnn] = pbh[i];
            *(uint4*)&sBl[bk[i] * BSTR + bnn] = pbl[i];
        }
        __syncthreads();
        if (kt + 1 < NKT) TG_LOAD(kt + 1)
#pragma unroll
        for (int ks = 0; ks < 2; ks++) {
            unsigned ah[4][4], al[4][4], bh[4][2], bl[4][2];
#pragma unroll
            for (int mi = 0; mi < 4; mi++) {
                int row = wm * 64 + mi * 16 + lrow;
                unsigned offA = (unsigned)(row * ASTR + ks * 16 + lko) * 2u;
                ldsm_x4(baseAh + offA, ah[mi]);
                ldsm_x4(baseAl + offA, al[mi]);
            }
#pragma unroll
            for (int ni = 0; ni < 4; ni++) {
                int rb = ks * 16 + lrow;
                unsigned offB = (unsigned)(rb * BSTR + wn * 32 + ni * 8) * 2u;
                ldsm_x2t(baseBh + offB, bh[ni]);
                ldsm_x2t(baseBl + offB, bl[ni]);
            }
#pragma unroll
            for (int mi = 0; mi < 4; mi++)
#pragma unroll
                for (int ni = 0; ni < 4; ni++) {
                    mma16816(acc[mi][ni], ah[mi], bh[ni]);
                    mma16816(acc[mi][ni], ah[mi], bl[ni]);
                    mma16816(acc[mi][ni], al[mi], bh[ni]);
                }
        }
    }

    // epilogue
    int g = lane >> 2, tig = lane & 3;
#pragma unroll
    for (int mi = 0; mi < 4; mi++) {
#pragma unroll
        for (int ni = 0; ni < 4; ni++) {
            int trow = t0m + wm * 64 + mi * 16 + g;
            size_t gr0 = (size_t)(bb * TOUT + trow) * N;
            size_t gr1 = gr0 + (size_t)8 * N;
            int gc = n0 + wn * 32 + ni * 8 + tig * 2;
            float* a = acc[mi][ni];
            if (EPI == 0) {
                *(float2*)(outF + gr0 + gc) = make_float2(a[0], a[1]);
                *(float2*)(outF + gr1 + gc) = make_float2(a[2], a[3]);
            } else {
                float b0 = bias[gc], b1 = bias[gc + 1];
                float v0 = gelu_exact(a[0] + b0), v1 = gelu_exact(a[1] + b1);
                float v2 = gelu_exact(a[2] + b0), v3 = gelu_exact(a[3] + b1);
                if (EPI == 1) {
                    *(float2*)(outF + gr0 + gc) = make_float2(v0, v1);
                    *(float2*)(outF + gr1 + gc) = make_float2(v2, v3);
                } else {
                    __nv_bfloat16 h0, l0, h1, l1;
                    fsplit(v0, h0, l0); fsplit(v1, h1, l1);
                    *(__nv_bfloat162*)(outHi + gr0 + gc) = __nv_bfloat162(h0, h1);
                    *(__nv_bfloat162*)(outLo + gr0 + gc) = __nv_bfloat162(l0, l1);
                    fsplit(v2, h0, l0); fsplit(v3, h1, l1);
                    *(__nv_bfloat162*)(outHi + gr1 + gc) = __nv_bfloat162(h0, h1);
                    *(__nv_bfloat162*)(outLo + gr1 + gc) = __nv_bfloat162(l0, l1);
                }
            }
        }
    }
}

// ---------------------------------------------------------------------------
// bias + ChannelNorm + ReLU + bf16-split (and optional fp32 out).
// one block per row (512 channels), 128 threads x 4 channels.
// ---------------------------------------------------------------------------
__global__ __launch_bounds__(128) void k_normsplit(
    const float* __restrict__ raw, const float* __restrict__ bias,
    const float* __restrict__ nw, const float* __restrict__ nb,
    float* __restrict__ outF,
    __nv_bfloat16* __restrict__ oh, __nv_bfloat16* __restrict__ ol) {
    __shared__ float sr[8];
    size_t row = blockIdx.x;
    int t = threadIdx.x, c0 = t * 4;
    float4 v = *(const float4*)(raw + row * CCH + c0);
    float4 b4 = *(const float4*)(bias + c0);
    v.x += b4.x; v.y += b4.y; v.z += b4.z; v.w += b4.w;
    float s1 = v.x + v.y + v.z + v.w;
    float s2 = v.x * v.x + v.y * v.y + v.z * v.z + v.w * v.w;
    int lane = t & 31, w = t >> 5;
#pragma unroll
    for (int o = 16; o > 0; o >>= 1) {
        s1 += __shfl_down_sync(0xffffffffu, s1, o);
        s2 += __shfl_down_sync(0xffffffffu, s2, o);
    }
    if (lane == 0) { sr[w] = s1; sr[w + 4] = s2; }
    __syncthreads();
    float S1 = sr[0] + sr[1] + sr[2] + sr[3];
    float S2 = sr[4] + sr[5] + sr[6] + sr[7];
    float mean = S1 * (1.f / 512.f);
    float var  = (S2 - S1 * S1 * (1.f / 512.f)) * (1.f / 511.f);
    float inv  = rsqrtf(var + 1e-5f);
    float4 g4 = *(const float4*)(nw + c0);
    float4 e4 = *(const float4*)(nb + c0);
    float y0 = fmaxf((v.x - mean) * inv * g4.x + e4.x, 0.f);
    float y1 = fmaxf((v.y - mean) * inv * g4.y + e4.y, 0.f);
    float y2 = fmaxf((v.z - mean) * inv * g4.z + e4.z, 0.f);
    float y3 = fmaxf((v.w - mean) * inv * g4.w + e4.w, 0.f);
    if (outF) *(float4*)(outF + row * CCH + c0) = make_float4(y0, y1, y2, y3);
    __nv_bfloat16 h0, l0, h1, l1;
    fsplit(y0, h0, l0); fsplit(y1, h1, l1);
    *(__nv_bfloat162*)(oh + row * CCH + c0) = __nv_bfloat162(h0, h1);
    *(__nv_bfloat162*)(ol + row * CCH + c0) = __nv_bfloat162(l0, l1);
    fsplit(y2, h0, l0); fsplit(y3, h1, l1);
    *(__nv_bfloat162*)(oh + row * CCH + c0 + 2) = __nv_bfloat162(h0, h1);
    *(__nv_bfloat162*)(ol + row * CCH + c0 + 2) = __nv_bfloat162(l0, l1);
}

// ---------------------------------------------------------------------------
// MLP head: imp = sigmoid(z2 @ w3 + b3) + 1e-5.  One warp per row.
// ---------------------------------------------------------------------------
__global__ __launch_bounds__(256) void k_mlp3(
    const float* __restrict__ z2, const float* __restrict__ w3,
    const float* __restrict__ b3, float* __restrict__ imp) {
    int row = blockIdx.x * 8 + (threadIdx.x >> 5);
    int lane = threadIdx.x & 31;
    const float* zr = z2 + (size_t)row * DMLP;
    float s = 0.f;
    for (int i = lane; i < DMLP; i += 32) s = fmaf(zr[i], w3[i], s);
#pragma unroll
    for (int o = 16; o > 0; o >>= 1) s += __shfl_down_sync(0xffffffffu, s, o);
    if (lane == 0) imp[row] = 1.f / (1.f + expf(-(s + b3[0]))) + 1e-5f;
}

// ---------------------------------------------------------------------------
// Normalize importance + inclusive cumsum. One block per batch.
// ---------------------------------------------------------------------------
__global__ __launch_bounds__(512) void k_scan(const float* __restrict__ imp,
                                              float* __restrict__ cs) {
    __shared__ float sa[512], sb[512];
    int b = blockIdx.x, t = threadIdx.x;
    sa[t] = imp[b * T3 + t];
    __syncthreads();
    float* src = sa;
    float* dst = sb;
    for (int off = 1; off < 512; off <<= 1) {
        float v = src[t] + ((t >= off) ? src[t - off] : 0.f);
        dst[t] = v;
        __syncthreads();
        float* tmp = src; src = dst; dst = tmp;
    }
    float scale = 256.f / src[511];
    cs[b * T3 + t] = src[t] * scale;
}

// ---------------------------------------------------------------------------
// Smartpool warp + final ChannelNorm + ReLU. Output [B][C][TN].
// ---------------------------------------------------------------------------
__global__ __launch_bounds__(512) void k_pool(
    const float* __restrict__ f, const float* __restrict__ cs,
    const float* __restrict__ nw, const float* __restrict__ nb,
    float* __restrict__ out) {
    __shared__ float scs[513];
    __shared__ float sred[64];
    int b = blockIdx.y, n = blockIdx.x, c = threadIdx.x;
    if (c == 0) scs[0] = 0.f;
    scs[c + 1] = cs[b * T3 + c];
    __syncthreads();
    float fn = (float)n;
    bool lastn = (n == TN - 1);
    int lo;
    {
        int a = 0, e = 512;
        while (a < e) { int m = (a + e) >> 1; if (scs[m + 1] > fn) e = m; else a = m + 1; }
        lo = a;
    }
    int hi = 512;
    if (!lastn) {
        int a = 0, e = 512;
        while (a < e) { int m = (a + e) >> 1; if (scs[m] < fn + 1.f) a = m + 1; else e = m; }
        hi = a;
    }
    float acc = 0.f;
    for (int t = lo; t < hi; t++) {
        float x1 = scs[t + 1] - fn, x0 = scs[t] - fn;
        float d1 = lastn ? fmaxf(x1, 0.f) : fminf(fmaxf(x1, 0.f), 1.f);
        float d0 = lastn ? fmaxf(x0, 0.f) : fminf(fmaxf(x0, 0.f), 1.f);
        acc = fmaf(d1 - d0, f[((size_t)(b * T3 + t)) * CCH + c], acc);
    }
    float2 s = block_reduce2(acc, acc * acc, sred);
    float mean = s.x * (1.f / 512.f);
    float var  = (s.y - s.x * s.x * (1.f / 512.f)) * (1.f / 511.f);
    float inv  = rsqrtf(var + 1e-5f);
    float v    = (acc - mean) * inv * nw[c] + nb[c];
    out[((size_t)(b * CCH + c)) * TN + n] = fmaxf(v, 0.f);
}

// ---------------------------------------------------------------------------
// Launch
// ---------------------------------------------------------------------------
extern "C" void kernel_launch(void* const* d_in, const int* in_sizes, int n_in,
                              void* d_out, int out_size) {
    (void)in_sizes; (void)n_in; (void)out_size;
    const float* x   = (const float*)d_in[0];
    const float* c0w = (const float*)d_in[1];
    const float* c0b = (const float*)d_in[2];
    const float* c1w = (const float*)d_in[3];
    const float* c1b = (const float*)d_in[4];
    const float* c2w = (const float*)d_in[5];
    const float* c2b = (const float*)d_in[6];
    const float* c3w = (const float*)d_in[7];
    const float* c3b = (const float*)d_in[8];
    const float* w1  = (const float*)d_in[9];
    const float* b1  = (const float*)d_in[10];
    const float* w2  = (const float*)d_in[11];
    const float* b2  = (const float*)d_in[12];
    const float* w3  = (const float*)d_in[13];
    const float* b3  = (const float*)d_in[14];
    const float* n0w = (const float*)d_in[15];
    const float* n0b = (const float*)d_in[16];
    const float* n1w = (const float*)d_in[17];
    const float* n1b = (const float*)d_in[18];
    const float* n2w = (const float*)d_in[19];
    const float* n2b = (const float*)d_in[20];
    const float* n3w = (const float*)d_in[21];
    const float* n3b = (const float*)d_in[22];
    const float* n4w = (const float*)d_in[23];
    const float* n4b = (const float*)d_in[24];
    float* out = (float*)d_out;

    __nv_bfloat16 *p_h0h, *p_h0l, *p_h1h, *p_h1l, *p_h2h, *p_h2l, *p_fh, *p_fl;
    __nv_bfloat16 *p_z1h, *p_z1l;
    __nv_bfloat16 *p_w1h, *p_w1l, *p_w2h, *p_w2l, *p_w3h, *p_w3l;
    __nv_bfloat16 *p_mw1h, *p_mw1l, *p_mw2h, *p_mw2l;
    float *p_f, *p_z2, *p_raw, *p_imp, *p_cs, *p_w0f;
    cudaGetSymbolAddress((void**)&p_h0h, g_h0h);  cudaGetSymbolAddress((void**)&p_h0l, g_h0l);
    cudaGetSymbolAddress((void**)&p_h1h, g_h1h);  cudaGetSymbolAddress((void**)&p_h1l, g_h1l);
    cudaGetSymbolAddress((void**)&p_h2h, g_h2h);  cudaGetSymbolAddress((void**)&p_h2l, g_h2l);
    cudaGetSymbolAddress((void**)&p_fh,  g_fh);   cudaGetSymbolAddress((void**)&p_fl,  g_fl);
    cudaGetSymbolAddress((void**)&p_z1h, g_z1h);  cudaGetSymbolAddress((void**)&p_z1l, g_z1l);
    cudaGetSymbolAddress((void**)&p_w1h, g_w1h);  cudaGetSymbolAddress((void**)&p_w1l, g_w1l);
    cudaGetSymbolAddress((void**)&p_w2h, g_w2h);  cudaGetSymbolAddress((void**)&p_w2l, g_w2l);
    cudaGetSymbolAddress((void**)&p_w3h, g_w3h);  cudaGetSymbolAddress((void**)&p_w3l, g_w3l);
    cudaGetSymbolAddress((void**)&p_mw1h, g_mw1h); cudaGetSymbolAddress((void**)&p_mw1l, g_mw1l);
    cudaGetSymbolAddress((void**)&p_mw2h, g_mw2h); cudaGetSymbolAddress((void**)&p_mw2l, g_mw2l);
    cudaGetSymbolAddress((void**)&p_f,   g_f);
    cudaGetSymbolAddress((void**)&p_z2,  g_z2);
    cudaGetSymbolAddress((void**)&p_raw, g_raw);
    cudaGetSymbolAddress((void**)&p_imp, g_imp);
    cudaGetSymbolAddress((void**)&p_cs,  g_cs);
    cudaGetSymbolAddress((void**)&p_w0f, g_w0f);

    // weight prep
    k_wsplit_conv<<<(8 * CCH * CCH) / 256, 256>>>(c1w, p_w1h, p_w1l, CCH, 8, 8 * CCH * CCH);
    k_wsplit_conv<<<(4 * CCH * CCH) / 256, 256>>>(c2w, p_w2h, p_w2l, CCH, 4, 4 * CCH * CCH);
    k_wsplit_conv<<<(4 * CCH * CCH) / 256, 256>>>(c3w, p_w3h, p_w3l, CCH, 4, 4 * CCH * CCH);
    k_w0trans<<<(10 * CCH + 255) / 256, 256>>>(c0w, p_w0f);
    k_split<<<(CCH * DMLP) / 256, 256>>>(w1, p_mw1h, p_mw1l, CCH * DMLP);
    k_split<<<(DMLP * DMLP) / 256, 256>>>(w2, p_mw2h, p_mw2l, DMLP * DMLP);

    // encoder
    k_conv0<<<dim3(T0 / 8, BATCH), 512>>>(x, p_w0f, c0b, n0w, n0b, p_h0h, p_h0l);
    // conv1: per batch M=T1, N=512, K=4096
    k_tgemm<8, 4, 2, 0><<<dim3(4, T1 / 128, BATCH), 256>>>(
        p_h0h, p_h0l, p_w1h, p_w1l, nullptr, p_raw, nullptr, nullptr,
        T0, T1, CCH, 8 * CCH, CCH);
    k_normsplit<<<BATCH * T1, 128>>>(p_raw, c1b, n1w, n1b, nullptr, p_h1h, p_h1l);
    // conv2
    k_tgemm<4, 2, 1, 0><<<dim3(4, T2 / 128, BATCH), 256>>>(
        p_h1h, p_h1l, p_w2h, p_w2l, nullptr, p_raw, nullptr, nullptr,
        T1, T2, CCH, 4 * CCH, CCH);
    k_normsplit<<<BATCH * T2, 128>>>(p_raw, c2b, n2w, n2b, nullptr, p_h2h, p_h2l);
    // conv3
    k_tgemm<4, 2, 1, 0><<<dim3(4, T3 / 128, BATCH), 256>>>(
        p_h2h, p_h2l, p_w3h, p_w3l, nullptr, p_raw, nullptr, nullptr,
        T2, T3, CCH, 4 * CCH, CCH);
    k_normsplit<<<BATCH * T3, 128>>>(p_raw, c3b, n3w, n3b, p_f, p_fh, p_fl);

    // importance MLP (tensor)
    k_tgemm<1, 1, 0, 2><<<dim3(DMLP / 128, (BATCH * T3) / 128, 1), 256>>>(
        p_fh, p_fl, p_mw1h, p_mw1l, b1, nullptr, p_z1h, p_z1l,
        BATCH * T3, BATCH * T3, DMLP, CCH, CCH);
    k_tgemm<1, 1, 0, 1><<<dim3(DMLP / 128, (BATCH * T3) / 128, 1), 256>>>(
        p_z1h, p_z1l, p_mw2h, p_mw2l, b2, p_z2, nullptr, nullptr,
        BATCH * T3, BATCH * T3, DMLP, DMLP, DMLP);
    k_mlp3<<<(BATCH * T3) / 8, 256>>>(p_z2, w3, b3, p_imp);
    k_scan<<<BATCH, 512>>>(p_imp, p_cs);

    // smartpool warp + final norm
    k_pool<<<dim3(TN, BATCH), 512>>>(p_f, p_cs, n4w, n4b, out);
}